// round 14
// baseline (speedup 1.0000x reference)
#include <cuda_runtime.h>
#include <cuda_bf16.h>

// DETR3D feature sampling. B=1, NC=6 cams, C=256, nq=900, 4 FPN levels
// (H,W): (116,200) (58,100) (29,50) (15,25).
// Output: ref3d[900,3] | sampled[256,900,6,1,4] | mask[900,6].
//
// Thread model (corner-pair lane sharing + level-pair float2 stores):
//   block = 192 threads = 8 queries x 6 cams x (2 level-pairs x 2 xsides).
//   xside = t&1  : which x column of the bilinear quad this lane loads.
//                  Lanes (t, t^1) handle the SAME sample; their column
//                  indices differ by 1 so both row loads coalesce into one
//                  L1 wavefront per LDG. Bilinear sum completes with one
//                  __shfl_xor(+) across the pair.
//   lpair = (t>>1)&1 : levels {2*lpair, 2*lpair+1}. Both levels are
//                  accumulated in the SAME channel iteration, and the
//                  xside==0 lane stores them as ONE float2 (the output
//                  minor dim is the level, stride 1; 8B aligned). The 16
//                  storing lanes cover one contiguous 128B line -> 1 store
//                  wavefront per warp-channel (was ~2 x 2 passes).
// Out-of-frustum samples (~87%) skip loads entirely (exact: reference
// multiplies those corners by valid=0). Corner indices clamped, invalid
// corner weights zeroed -> branch-free channel loop. Channel loop fully
// unrolled: per-channel addresses fold into LDG immediate offsets.
//
// R13: identical to the R12 candidate — the R12 bench died in the broker
// (container failure) before measuring it; re-benching unchanged per rigor.md.

#define FS_EPS 1e-5f
#define NQ 900
#define NCAM 6
#define NCH 256
#define QPB 8              // queries per block
#define CPB 16             // channels per chunk (grid.y)
#define THREADS (QPB * NCAM * 4)   // 192

__global__ __launch_bounds__(THREADS, 8)
void fs_sample_kernel(
    const float* __restrict__ f0,   // [6,256,116,200]
    const float* __restrict__ f1,   // [6,256, 58,100]
    const float* __restrict__ f2,   // [6,256, 29, 50]
    const float* __restrict__ f3,   // [6,256, 15, 25]
    const float* __restrict__ ref,  // [900,3]
    const float* __restrict__ pc,   // [6]
    const float* __restrict__ img,  // [2] = {H=928, W=1600}
    const float* __restrict__ l2i,  // [6,4,4]
    float* __restrict__ out)
{
    const int t     = threadIdx.x;       // 0..191
    const int xside = t & 1;             // which x column of the bilinear pair
    const int lpair = (t >> 1) & 1;      // levels {2*lpair, 2*lpair+1}
    const int s     = t >> 2;            // 0..47 = qsub*6 + n
    const int qsub  = s / NCAM;
    const int n     = s - qsub * NCAM;
    const int q     = blockIdx.x * QPB + qsub;
    const int cbase = blockIdx.y * CPB;

    float* sampled = out + NQ * 3;                       // 2700
    float* maskout = out + NQ * 3 + NCH * NQ * NCAM * 4; // 2700 + 5529600

    // ref3d passthrough (channel-chunk 0 blocks only)
    if (blockIdx.y == 0 && t < QPB * 3) {
        int qq = blockIdx.x * QPB + t / 3;
        if (qq < NQ) out[qq * 3 + (t % 3)] = ref[qq * 3 + (t % 3)];
    }

    const bool active = (q < NQ);

    // --- projection (level-independent, matches reference arithmetic) ---
    float gx = 0.f, gy = 0.f;
    if (active) {
        const float rx = ref[q * 3 + 0];
        const float ry = ref[q * 3 + 1];
        const float rz = ref[q * 3 + 2];
        const float px = rx * (pc[3] - pc[0]) + pc[0];
        const float py = ry * (pc[4] - pc[1]) + pc[1];
        const float pz = rz * (pc[5] - pc[2]) + pc[2];
        const float* M = l2i + n * 16;
        const float c0 = M[0] * px + M[1] * py + M[2]  * pz + M[3];
        const float c1 = M[4] * px + M[5] * py + M[6]  * pz + M[7];
        const float c2 = M[8] * px + M[9] * py + M[10] * pz + M[11];
        const float zd = fmaxf(c2, FS_EPS);
        gx = (c0 / zd / img[1] - 0.5f) * 2.0f;
        gy = (c1 / zd / img[0] - 0.5f) * 2.0f;

        if ((t & 3) == 0 && blockIdx.y == 0) {
            const bool m = (c2 > FS_EPS) &&
                           (gx > -1.0f) && (gx < 1.0f) &&
                           (gy > -1.0f) && (gy < 1.0f);
            maskout[q * NCAM + n] = m ? 1.0f : 0.0f;
        }
    }

    // --- bilinear setup for this lane's two levels (lA = 2*lp, lB = 2*lp+1) ---
    int   jA0 = 0, jA1 = 0, jB0 = 0, jB1 = 0;
    float wA0 = 0.f, wA1 = 0.f, wB0 = 0.f, wB1 = 0.f;
    bool  dlA = false, dlB = false;

    const int   lA  = 2 * lpair;                 // 0 or 2
    const int   WA  = lpair ? 50 : 200;
    const int   HA  = lpair ? 29 : 116;
    const int   WB  = lpair ? 25 : 100;
    const int   HB  = lpair ? 15 : 58;
    const int   HWA = WA * HA;
    const int   HWB = WB * HB;
    const float* fA = lpair ? f2 : f0;
    const float* fB = lpair ? f3 : f1;

    if (active) {
        #pragma unroll
        for (int half = 0; half < 2; half++) {
            const int Wl = half ? WB : WA;
            const int Hl = half ? HB : HA;

            const float ix  = ((gx + 1.0f) * (float)Wl - 1.0f) * 0.5f;
            const float iy  = ((gy + 1.0f) * (float)Hl - 1.0f) * 0.5f;
            const float ix0 = floorf(ix);
            const float iy0 = floorf(iy);
            const float wx1 = ix - ix0;
            const float wy1 = iy - iy0;
            const float wx0 = 1.0f - wx1;
            const float wy0 = 1.0f - wy1;

            // side validity (NaN comparisons false -> anyvalid false)
            const bool vx0 = (ix0        >= 0.0f) && (ix0        <= (float)(Wl - 1));
            const bool vx1 = (ix0 + 1.0f >= 0.0f) && (ix0 + 1.0f <= (float)(Wl - 1));
            const bool vy0 = (iy0        >= 0.0f) && (iy0        <= (float)(Hl - 1));
            const bool vy1 = (iy0 + 1.0f >= 0.0f) && (iy0 + 1.0f <= (float)(Hl - 1));
            const bool anyvalid = (vx0 | vx1) & (vy0 | vy1);  // same for both pair lanes

            if (anyvalid) {
                // anyvalid implies ix0 in [-1,Wl-1], iy0 in [-1,Hl-1] -> safe int conv
                const int ixi = (int)ix0;
                const int iyi = (int)iy0;
                const int xc0 = max(ixi,     0);
                const int xc1 = min(ixi + 1, Wl - 1);
                const int yr0 = max(iyi,     0) * Wl;
                const int yr1 = min(iyi + 1, Hl - 1) * Wl;

                const int   xs  = xside ? xc1 : xc0;   // this lane's column
                const bool  vxs = xside ? vx1 : vx0;
                const float wxs = xside ? wx1 : wx0;
                const int   k0  = yr0 + xs;
                const int   k1  = yr1 + xs;
                const float u0  = (vy0 && vxs) ? wy0 * wxs : 0.f;
                const float u1  = (vy1 && vxs) ? wy1 * wxs : 0.f;
                if (half == 0) { jA0 = k0; jA1 = k1; wA0 = u0; wA1 = u1; dlA = true; }
                else           { jB0 = k0; jB1 = k1; wB0 = u0; wB1 = u1; dlB = true; }
            }
        }
    }

    // --- channel loop ---
    // feat element: f[(n*256 + c)*HW + j]
    // out element : sampled[((c*900 + q)*6 + n)*4 + l],  l = 2*lpair (+0/+1)
    const float* pA = fA + (size_t)(n * NCH + cbase) * (size_t)HWA;
    const float* pB = fB + (size_t)(n * NCH + cbase) * (size_t)HWB;
    float*       op = sampled + ((size_t)cbase * NQ + q) * (NCAM * 4) + n * 4 + lA;
    const bool   dostore = active && (xside == 0);

    #pragma unroll
    for (int cc = 0; cc < CPB; cc++) {
        float a = 0.0f, b = 0.0f;
        if (dlA) {
            // pair lanes' j differ by 1 -> same 128B line, one wavefront per LDG
            a = fmaf(wA0, __ldg(pA + cc * HWA + jA0), wA1 * __ldg(pA + cc * HWA + jA1));
        }
        if (dlB) {
            b = fmaf(wB0, __ldg(pB + cc * HWB + jB0), wB1 * __ldg(pB + cc * HWB + jB1));
        }
        // complete bilinear sums across the (xc0, xc1) lane pair
        a += __shfl_xor_sync(0xffffffffu, a, 1);
        b += __shfl_xor_sync(0xffffffffu, b, 1);
        if (dostore) {
            // 16 lanes * 8B contiguous -> one 128B line per warp store
            *reinterpret_cast<float2*>(op + (size_t)cc * (NQ * NCAM * 4)) =
                make_float2(a, b);
        }
    }
}

extern "C" void kernel_launch(void* const* d_in, const int* in_sizes, int n_in,
                              void* d_out, int out_size) {
    const float* f0  = (const float*)d_in[0];
    const float* f1  = (const float*)d_in[1];
    const float* f2  = (const float*)d_in[2];
    const float* f3  = (const float*)d_in[3];
    const float* ref = (const float*)d_in[4];
    const float* pc  = (const float*)d_in[5];
    const float* img = (const float*)d_in[6];
    const float* l2i = (const float*)d_in[7];
    float* out = (float*)d_out;

    dim3 grid((NQ + QPB - 1) / QPB, NCH / CPB);  // (113, 16) = 1808 blocks
    fs_sample_kernel<<<grid, THREADS>>>(f0, f1, f2, f3, ref, pc, img, l2i, out);
}